// round 2
// baseline (speedup 1.0000x reference)
#include <cuda_runtime.h>
#include <cuda_bf16.h>

// BERTLatticeEmbedding: ragged segment mean-pool.
// hidden   [B,S,H] f32, word_ids [B,S] int32 (sorted non-decreasing per row),
// out      [B,T,H] f32 where out[b,w,:] = mean over pieces s with word_ids[b,s]==w
// (zero if no pieces).
//
// B=64, S=512, H=768, T=400 (fixed shapes for this problem).

#define B_DIM 64
#define S_DIM 512
#define H_DIM 768
#define T_DIM 400
#define H4 (H_DIM / 4)   // 192 float4 per row

__global__ __launch_bounds__(H4) void pool_kernel(
    const float* __restrict__ hidden,
    const int* __restrict__ word_ids,
    float* __restrict__ out)
{
    const int bw = blockIdx.x;          // 0 .. B*T-1
    const int b  = bw / T_DIM;
    const int w  = bw % T_DIM;

    const int* __restrict__ row = word_ids + b * S_DIM;

    // lower_bound(w): first s with row[s] >= w
    int lo = 0, hi = S_DIM;
    while (lo < hi) {
        int mid = (lo + hi) >> 1;
        if (row[mid] < w) lo = mid + 1; else hi = mid;
    }
    const int start = lo;

    // lower_bound(w+1): first s with row[s] >= w+1
    hi = S_DIM;
    while (lo < hi) {
        int mid = (lo + hi) >> 1;
        if (row[mid] < w + 1) lo = mid + 1; else hi = mid;
    }
    const int end = lo;

    const int tid = threadIdx.x;        // 0..191
    const float4* __restrict__ hin =
        reinterpret_cast<const float4*>(hidden + (size_t)b * S_DIM * H_DIM);

    float4 acc = make_float4(0.f, 0.f, 0.f, 0.f);
    for (int s = start; s < end; ++s) {
        float4 v = hin[(size_t)s * H4 + tid];
        acc.x += v.x; acc.y += v.y; acc.z += v.z; acc.w += v.w;
    }

    const int cnt = end - start;
    const float inv = 1.0f / (float)(cnt > 0 ? cnt : 1);
    acc.x *= inv; acc.y *= inv; acc.z *= inv; acc.w *= inv;

    float4* __restrict__ outp =
        reinterpret_cast<float4*>(out + ((size_t)b * T_DIM + w) * H_DIM);
    outp[tid] = acc;
}

extern "C" void kernel_launch(void* const* d_in, const int* in_sizes, int n_in,
                              void* d_out, int out_size)
{
    const float* hidden   = (const float*)d_in[0];
    const int*   word_ids = (const int*)d_in[1];
    // d_in[2] = num_tokens scalar (device); T is fixed at 400 for this problem.
    float* out = (float*)d_out;

    pool_kernel<<<B_DIM * T_DIM, H4>>>(hidden, word_ids, out);
}

// round 3
// speedup vs baseline: 1.8595x; 1.8595x over previous
#include <cuda_runtime.h>
#include <cuda_bf16.h>

// BERTLatticeEmbedding: ragged segment mean-pool.
// hidden [B,S,H] f32, word_ids [B,S] int32 (sorted non-decreasing per row),
// out    [B,T,H] f32: out[b,w,:] = mean over pieces s with word_ids[b,s]==w
// (zeros if no pieces).  B=64, S=512, H=768, T=400.
//
// R2 design: block = (b, 16-word tile). word_ids row cached in SMEM; 17
// threads compute segment boundaries (shared: end(w)=start(w+1)). Payload:
// warp-per-word, 6 float4 accumulators per lane (H=768 = 32 lanes * 6 * 4).

#define B_DIM 64
#define S_DIM 512
#define H_DIM 768
#define T_DIM 400
#define H4    (H_DIM / 4)      // 192 float4 per row
#define TILE_W 16
#define WPB    4               // warps per block
#define THREADS (WPB * 32)     // 128
#define NTILES (T_DIM / TILE_W) // 25

__global__ __launch_bounds__(THREADS) void pool_kernel(
    const float* __restrict__ hidden,
    const int* __restrict__ word_ids,
    float* __restrict__ out)
{
    __shared__ int s_row[S_DIM];
    __shared__ int s_start[TILE_W + 1];

    const int b     = blockIdx.y;
    const int wbase = blockIdx.x * TILE_W;
    const int tid   = threadIdx.x;

    // Cooperative load of this sample's word_ids row (2 KB) into SMEM.
    const int* __restrict__ grow = word_ids + b * S_DIM;
    #pragma unroll
    for (int i = tid; i < S_DIM; i += THREADS) s_row[i] = grow[i];
    __syncthreads();

    // Segment boundaries: s_start[i] = lower_bound(wbase + i) over s_row.
    if (tid <= TILE_W) {
        const int target = wbase + tid;
        int lo = 0, hi = S_DIM;
        while (lo < hi) {
            int mid = (lo + hi) >> 1;
            if (s_row[mid] < target) lo = mid + 1; else hi = mid;
        }
        s_start[tid] = lo;
    }
    __syncthreads();

    const int warp = tid >> 5;
    const int lane = tid & 31;

    const float4* __restrict__ hin =
        reinterpret_cast<const float4*>(hidden + (size_t)b * S_DIM * H_DIM);

    #pragma unroll
    for (int i = warp; i < TILE_W; i += WPB) {
        const int st  = s_start[i];
        const int en  = s_start[i + 1];

        float4 acc0 = make_float4(0.f,0.f,0.f,0.f);
        float4 acc1 = acc0, acc2 = acc0, acc3 = acc0, acc4 = acc0, acc5 = acc0;

        for (int s = st; s < en; ++s) {
            const float4* __restrict__ p = hin + (size_t)s * H4 + lane;
            float4 v0 = p[0 * 32];
            float4 v1 = p[1 * 32];
            float4 v2 = p[2 * 32];
            float4 v3 = p[3 * 32];
            float4 v4 = p[4 * 32];
            float4 v5 = p[5 * 32];
            acc0.x += v0.x; acc0.y += v0.y; acc0.z += v0.z; acc0.w += v0.w;
            acc1.x += v1.x; acc1.y += v1.y; acc1.z += v1.z; acc1.w += v1.w;
            acc2.x += v2.x; acc2.y += v2.y; acc2.z += v2.z; acc2.w += v2.w;
            acc3.x += v3.x; acc3.y += v3.y; acc3.z += v3.z; acc3.w += v3.w;
            acc4.x += v4.x; acc4.y += v4.y; acc4.z += v4.z; acc4.w += v4.w;
            acc5.x += v5.x; acc5.y += v5.y; acc5.z += v5.z; acc5.w += v5.w;
        }

        const int cnt = en - st;
        const float inv = 1.0f / (float)(cnt > 0 ? cnt : 1);
        acc0.x *= inv; acc0.y *= inv; acc0.z *= inv; acc0.w *= inv;
        acc1.x *= inv; acc1.y *= inv; acc1.z *= inv; acc1.w *= inv;
        acc2.x *= inv; acc2.y *= inv; acc2.z *= inv; acc2.w *= inv;
        acc3.x *= inv; acc3.y *= inv; acc3.z *= inv; acc3.w *= inv;
        acc4.x *= inv; acc4.y *= inv; acc4.z *= inv; acc4.w *= inv;
        acc5.x *= inv; acc5.y *= inv; acc5.z *= inv; acc5.w *= inv;

        float4* __restrict__ op =
            reinterpret_cast<float4*>(out + ((size_t)b * T_DIM + wbase + i) * H_DIM) + lane;
        op[0 * 32] = acc0;
        op[1 * 32] = acc1;
        op[2 * 32] = acc2;
        op[3 * 32] = acc3;
        op[4 * 32] = acc4;
        op[5 * 32] = acc5;
    }
}

extern "C" void kernel_launch(void* const* d_in, const int* in_sizes, int n_in,
                              void* d_out, int out_size)
{
    const float* hidden   = (const float*)d_in[0];
    const int*   word_ids = (const int*)d_in[1];
    float* out = (float*)d_out;

    dim3 grid(NTILES, B_DIM);
    pool_kernel<<<grid, THREADS>>>(hidden, word_ids, out);
}